// round 13
// baseline (speedup 1.0000x reference)
#include <cuda_runtime.h>
#include <cuda_fp16.h>
#include <cstdint>

#define NN    30000
#define DD    32
#define HH    128
#define KD    10
#define KPAD  144            // 142 used + 2 zero
#define SP    152            // smem k-pitch in halves (304 B, ldmatrix conflict-free)
#define FUSED_SMEM (2 * 128 * SP * 2 + 8 * 32 * 8)   // A + B tiles + meta = 79872 B

__device__ __half g_feat[NN * HH];          // fp16 feature cache
__device__ __half g_Bth[128 * KPAD];        // B^T fp16 [n][k] (zero-init)

// ------------------------------------------------- prep: build B^T fp16
__global__ void prep_kernel(const float* __restrict__ W0, const float* __restrict__ b0,
                            const float* __restrict__ W1, const float* __restrict__ b1,
                            const float* __restrict__ W2, const float* __restrict__ b2,
                            const float* __restrict__ Wt3, const float* __restrict__ Wt4) {
    int r = blockIdx.x, j = threadIdx.x;
    float v;
    if (r < 128)        v = W2[r * HH + j];
    else if (r < 130)   v = W0[(r - 128) * HH + j];
    else if (r < 140)   v = W1[(r - 130) * HH + j];
    else if (r == 140) {                     // c = relu(Wt4) @ Wt3
        float acc = 0.f;
#pragma unroll 8
        for (int h = 0; h < HH; ++h) {
            float t = Wt4[h];
            t = t > 0.f ? t : 0.f;
            acc += t * Wt3[h * HH + j];
        }
        v = acc;
    } else              v = b0[j] + b1[j] + b2[j];   // r == 141: bias row
    g_Bth[j * KPAD + r] = __float2half(v);
}

// ------------------------------------------------- fp32 -> fp16 feature
__global__ void convert_kernel(const float* __restrict__ f) {
    int i = blockIdx.x * 256 + threadIdx.x;
    float4 v = ((const float4*)f)[i];
    __half2 h0 = __float22half2_rn(make_float2(v.x, v.y));
    __half2 h1 = __float22half2_rn(make_float2(v.z, v.w));
    uint2 o;
    o.x = *(unsigned*)&h0;
    o.y = *(unsigned*)&h1;
    ((uint2*)g_feat)[i] = o;
}

// ------------------------------------------------- fused gather + HMMA GEMM
__device__ __forceinline__ uint32_t s2u(const void* p) {
    uint32_t a;
    asm("{ .reg .u64 t; cvta.to.shared.u64 t, %1; cvt.u32.u64 %0, t; }" : "=r"(a) : "l"(p));
    return a;
}

__global__ void __launch_bounds__(256, 2)
fused_kernel(const float* __restrict__ x,  const float* __restrict__ label,
             const float* __restrict__ w,  const float* __restrict__ et,
             const int*   __restrict__ src, float* __restrict__ out) {
    extern __shared__ __half sm[];
    __half* smA = sm;                              // [128 m][SP]
    __half* smB = sm + 128 * SP;                   // [128 n][SP]
    float2* meta = (float2*)(sm + 2 * 128 * SP);   // [8 warps][32]

    const int tid  = threadIdx.x;
    const int wid  = tid >> 5, lane = tid & 31;
    const int n0   = blockIdx.x * 128;

    // -------- prefetch B^T tile via cp.async (overlaps with gather below)
    {
        const __half* sBg = g_Bth;
#pragma unroll
        for (int t = 0; t < 9; ++t) {
            int i = t * 256 + tid;
            int row = i / 18, q = i % 18;          // 18 float4 per 144-half row
            uint32_t dst = s2u(smB + row * SP + q * 8);
            const void* srcp = sBg + i * 8;
            asm volatile("cp.async.cg.shared.global [%0], [%1], 16;"
                         :: "r"(dst), "l"(srcp));
        }
        asm volatile("cp.async.commit_group;" ::: "memory");
    }

    // -------- gather phase: each warp produces 16 A rows, written straight to smA
    const uint2* fp = (const uint2*)g_feat;
#pragma unroll 1
    for (int it = 0; it < 16; ++it) {
        const int m  = wid * 16 + it;
        const int n  = n0 + m;
        const int nn = n < NN ? n : 0;             // clamp: stores guarded later
        const int base = nn * DD + lane;

        int   s_l = src[base];
        float e_l = ((const float2*)et)[base].x;
        float S   = w[base] * e_l;
#pragma unroll
        for (int o = 16; o; o >>= 1) S += __shfl_xor_sync(0xffffffffu, S, o);
        meta[wid * 32 + lane] = make_float2(e_l, __int_as_float(s_l));
        __syncwarp();

        float2 a0 = make_float2(0.f, 0.f), a1 = make_float2(0.f, 0.f);
#pragma unroll
        for (int d = 0; d < DD; ++d) {
            float2 me = meta[wid * 32 + d];
            int   s = __float_as_int(me.y);
            float e = me.x;
            uint2 q = __ldg(fp + s * (HH / 4) + lane);
            float2 f0 = __half22float2(*(__half2*)&q.x);
            float2 f1 = __half22float2(*(__half2*)&q.y);
            a0.x += f0.x * e; a0.y += f0.y * e;
            a1.x += f1.x * e; a1.y += f1.y * e;
        }

        __half* Ar = smA + m * SP;
        {
            __half2 h0 = __float22half2_rn(a0);
            __half2 h1 = __float22half2_rn(a1);
            uint2 o; o.x = *(unsigned*)&h0; o.y = *(unsigned*)&h1;
            *(uint2*)(Ar + lane * 4) = o;          // k = 4*lane .. 4*lane+3
        }
        float ev;
        if (lane < 2)        ev = x[nn * 2 + lane];
        else if (lane < 12)  ev = label[nn * KD + lane - 2];
        else if (lane == 12) ev = S;
        else if (lane == 13) ev = 1.0f;
        else                 ev = 0.0f;            // k = 142,143 zero-pad
        if (lane < 16)
            Ar[128 + lane] = __float2half(ev);     // k = 128..143
        __syncwarp();
    }

    asm volatile("cp.async.wait_group 0;" ::: "memory");
    __syncthreads();

    // -------- HMMA phase: warp grid 4 (m) x 2 (n); warp tile 32m x 64n
    const int wm = (wid >> 1) * 32;
    const int wn = (wid & 1) * 64;

    const uint32_t smA_u = s2u(smA), smB_u = s2u(smB);
    const uint32_t abase = smA_u + (uint32_t)(wm + (lane & 15)) * (SP * 2) + (lane >> 4) * 16;
    const uint32_t bbase = smB_u + (uint32_t)(wn + (lane & 7) + ((lane >> 4) << 3)) * (SP * 2)
                                 + ((lane >> 3) & 1) * 16;

    float c[2][8][4];
#pragma unroll
    for (int mt = 0; mt < 2; ++mt)
#pragma unroll
        for (int nt = 0; nt < 8; ++nt)
#pragma unroll
            for (int q = 0; q < 4; ++q) c[mt][nt][q] = 0.f;

#pragma unroll
    for (int ks = 0; ks < 9; ++ks) {
        const uint32_t kb = ks * 32;               // k0*2 bytes
        uint32_t a[2][4];
#pragma unroll
        for (int mt = 0; mt < 2; ++mt)
            asm volatile("ldmatrix.sync.aligned.m8n8.x4.shared.b16 {%0,%1,%2,%3}, [%4];"
                         : "=r"(a[mt][0]), "=r"(a[mt][1]), "=r"(a[mt][2]), "=r"(a[mt][3])
                         : "r"(abase + mt * 16 * (SP * 2) + kb));
#pragma unroll
        for (int ntp = 0; ntp < 4; ++ntp) {
            uint32_t b0, b1, b2, b3;
            asm volatile("ldmatrix.sync.aligned.m8n8.x4.shared.b16 {%0,%1,%2,%3}, [%4];"
                         : "=r"(b0), "=r"(b1), "=r"(b2), "=r"(b3)
                         : "r"(bbase + ntp * 16 * (SP * 2) + kb));
#pragma unroll
            for (int mt = 0; mt < 2; ++mt) {
                asm volatile(
                    "mma.sync.aligned.m16n8k16.row.col.f32.f16.f16.f32 "
                    "{%0,%1,%2,%3}, {%4,%5,%6,%7}, {%8,%9}, {%0,%1,%2,%3};"
                    : "+f"(c[mt][2 * ntp][0]), "+f"(c[mt][2 * ntp][1]),
                      "+f"(c[mt][2 * ntp][2]), "+f"(c[mt][2 * ntp][3])
                    : "r"(a[mt][0]), "r"(a[mt][1]), "r"(a[mt][2]), "r"(a[mt][3]),
                      "r"(b0), "r"(b1));
                asm volatile(
                    "mma.sync.aligned.m16n8k16.row.col.f32.f16.f16.f32 "
                    "{%0,%1,%2,%3}, {%4,%5,%6,%7}, {%8,%9}, {%0,%1,%2,%3};"
                    : "+f"(c[mt][2 * ntp + 1][0]), "+f"(c[mt][2 * ntp + 1][1]),
                      "+f"(c[mt][2 * ntp + 1][2]), "+f"(c[mt][2 * ntp + 1][3])
                    : "r"(a[mt][0]), "r"(a[mt][1]), "r"(a[mt][2]), "r"(a[mt][3]),
                      "r"(b2), "r"(b3));
            }
        }
    }

    // -------- epilogue: relu + store
#pragma unroll
    for (int mt = 0; mt < 2; ++mt) {
        const int row0 = n0 + wm + mt * 16 + (lane >> 2);
#pragma unroll
        for (int nt = 0; nt < 8; ++nt) {
            const int col = wn + nt * 8 + (lane & 3) * 2;
            if (row0 < NN) {
                float2 v;
                v.x = fmaxf(c[mt][nt][0], 0.f);
                v.y = fmaxf(c[mt][nt][1], 0.f);
                *(float2*)(out + (size_t)row0 * HH + col) = v;
            }
            if (row0 + 8 < NN) {
                float2 v;
                v.x = fmaxf(c[mt][nt][2], 0.f);
                v.y = fmaxf(c[mt][nt][3], 0.f);
                *(float2*)(out + (size_t)(row0 + 8) * HH + col) = v;
            }
        }
    }
}

// ------------------------------------------------- launch
extern "C" void kernel_launch(void* const* d_in, const int* in_sizes, int n_in,
                              void* d_out, int out_size) {
    const float* feature = (const float*)d_in[0];
    const float* x       = (const float*)d_in[1];
    const float* label   = (const float*)d_in[2];
    const float* w       = (const float*)d_in[3];
    const float* et      = (const float*)d_in[4];
    const int*   src     = (const int*)  d_in[5];
    const float* W0      = (const float*)d_in[6];
    const float* b0      = (const float*)d_in[7];
    const float* W1      = (const float*)d_in[8];
    const float* b1      = (const float*)d_in[9];
    const float* W2      = (const float*)d_in[10];
    const float* b2      = (const float*)d_in[11];
    const float* Wt3     = (const float*)d_in[12];
    const float* Wt4     = (const float*)d_in[13];
    float* out = (float*)d_out;

    cudaFuncSetAttribute(fused_kernel, cudaFuncAttributeMaxDynamicSharedMemorySize,
                         FUSED_SMEM);

    prep_kernel<<<142, HH>>>(W0, b0, W1, b1, W2, b2, Wt3, Wt4);
    convert_kernel<<<(NN * HH / 4) / 256, 256>>>(feature);                 // 3750 blocks
    fused_kernel<<<(NN + 127) / 128, 256, FUSED_SMEM>>>(x, label, w, et, src, out);
}

// round 16
// speedup vs baseline: 1.2535x; 1.2535x over previous
#include <cuda_runtime.h>
#include <cuda_fp16.h>
#include <cstdint>

#define NN    30000
#define DD    32
#define HH    128
#define KD    10
#define NPAD  30080          // 235 * 128
#define KPAD  144            // 142 used + 2 zero
#define SP    152            // smem k-pitch in halves (304 B, ldmatrix conflict-free)
#define GEMM_SMEM (2 * 128 * SP * 2)   // 77824 B
#define NCONV (NN * HH / 4 / 256)      // 3750 convert blocks

__device__ __half g_feat[NN * HH];          // fp16 feature cache
__device__ __half g_Ah[NPAD * KPAD];        // A fp16 row-major (zero-init)
__device__ __half g_Bth[128 * KPAD];        // B^T fp16 [n][k] (zero-init)

// ------------------------------------------------- convert + prep in one grid
// blocks 0..3749: fp32->fp16 feature convert.
// blocks 3750..3891: build B^T row r = bid-3750 (c-row uses 256-thread split-K).
__global__ void __launch_bounds__(256)
pc_kernel(const float* __restrict__ f,
          const float* __restrict__ W0, const float* __restrict__ b0,
          const float* __restrict__ W1, const float* __restrict__ b1,
          const float* __restrict__ W2, const float* __restrict__ b2,
          const float* __restrict__ Wt3, const float* __restrict__ Wt4) {
    const int bid = blockIdx.x, tid = threadIdx.x;
    if (bid < NCONV) {
        int i = bid * 256 + tid;
        float4 v = ((const float4*)f)[i];
        __half2 h0 = __float22half2_rn(make_float2(v.x, v.y));
        __half2 h1 = __float22half2_rn(make_float2(v.z, v.w));
        uint2 o;
        o.x = *(unsigned*)&h0;
        o.y = *(unsigned*)&h1;
        ((uint2*)g_feat)[i] = o;
        return;
    }
    const int r = bid - NCONV;          // 0..141
    if (r == 140) {                     // c = relu(Wt4) @ Wt3, split-K over 2 halves
        __shared__ float part[256];
        const int j = tid & 127, half = tid >> 7;
        float acc = 0.f;
#pragma unroll 8
        for (int h = half * 64; h < half * 64 + 64; ++h) {
            float t = Wt4[h];
            t = t > 0.f ? t : 0.f;
            acc += t * Wt3[h * HH + j];
        }
        part[tid] = acc;
        __syncthreads();
        if (tid < 128)
            g_Bth[j * KPAD + 140] = __float2half(part[tid] + part[tid + 128]);
        return;
    }
    if (tid >= 128) return;
    const int j = tid;
    float v;
    if (r < 128)        v = W2[r * HH + j];
    else if (r < 130)   v = W0[(r - 128) * HH + j];
    else if (r < 140)   v = W1[(r - 130) * HH + j];
    else                v = b0[j] + b1[j] + b2[j];   // r == 141: bias row
    g_Bth[j * KPAD + r] = __float2half(v);
}

// ------------------------------------------------- gather: 1 warp / node
__global__ void __launch_bounds__(256, 3)
gather_kernel(const float* __restrict__ x,  const float* __restrict__ label,
              const float* __restrict__ w,  const float* __restrict__ et,
              const int*   __restrict__ src) {
    __shared__ float2 meta[8][DD];
    const int wp = threadIdx.x >> 5, lane = threadIdx.x & 31;
    const int n  = blockIdx.x * 8 + wp;            // 3750 * 8 == 30000

    const int base = n * DD + lane;
    int   s_l = src[base];
    float e_l = ((const float2*)et)[base].x;
    float S   = w[base] * e_l;
#pragma unroll
    for (int o = 16; o; o >>= 1) S += __shfl_xor_sync(0xffffffffu, S, o);
    meta[wp][lane] = make_float2(e_l, __int_as_float(s_l));
    __syncwarp();

    const uint2* fp = (const uint2*)g_feat;
    float2 a0 = make_float2(0.f, 0.f), a1 = make_float2(0.f, 0.f);
#pragma unroll
    for (int d = 0; d < DD; ++d) {
        float2 me = meta[wp][d];
        int   s = __float_as_int(me.y);
        float e = me.x;
        uint2 q = __ldg(fp + s * (HH / 4) + lane);
        float2 f0 = __half22float2(*(__half2*)&q.x);
        float2 f1 = __half22float2(*(__half2*)&q.y);
        a0.x += f0.x * e; a0.y += f0.y * e;
        a1.x += f1.x * e; a1.y += f1.y * e;
    }

    __half* Ar = g_Ah + (size_t)n * KPAD;
    {
        __half2 h0 = __float22half2_rn(a0);
        __half2 h1 = __float22half2_rn(a1);
        uint2 o; o.x = *(unsigned*)&h0; o.y = *(unsigned*)&h1;
        *(uint2*)(Ar + lane * 4) = o;              // k = 4*lane .. 4*lane+3
    }
    float ev;
    if (lane < 2)        ev = x[n * 2 + lane];
    else if (lane < 12)  ev = label[n * KD + lane - 2];
    else if (lane == 12) ev = S;
    else                 ev = 1.0f;
    if (lane < 14)
        Ar[128 + lane] = __float2half(ev);         // k = 128..141
}

// ------------------------------------------------- HMMA GEMM: 128x128 tile / CTA
__device__ __forceinline__ uint32_t s2u(const void* p) {
    uint32_t a;
    asm("{ .reg .u64 t; cvta.to.shared.u64 t, %1; cvt.u32.u64 %0, t; }" : "=r"(a) : "l"(p));
    return a;
}

__global__ void __launch_bounds__(256, 2)
gemm_kernel(float* __restrict__ out) {
    extern __shared__ __half sm[];
    __half* smA = sm;                 // [128 m][SP]
    __half* smB = sm + 128 * SP;      // [128 n][SP]

    const int tid  = threadIdx.x;
    const int wid  = tid >> 5, lane = tid & 31;
    const int n0   = blockIdx.x * 128;

    // stage A tile + B tile: 2304 float4 each (9 per thread)
    {
        const float4* sAg = (const float4*)(g_Ah + (size_t)n0 * KPAD);
        const float4* sBg = (const float4*)g_Bth;
#pragma unroll
        for (int t = 0; t < 9; ++t) {
            int i = t * 256 + tid;
            int row = i / 18, q = i % 18;          // 18 float4 per 144-half row
            *(float4*)(smA + row * SP + q * 8) = __ldg(sAg + i);
            *(float4*)(smB + row * SP + q * 8) = __ldg(sBg + i);
        }
    }
    __syncthreads();

    // warp grid: 4 (m) x 2 (n); warp tile 32m x 64n
    const int wm = (wid >> 1) * 32;
    const int wn = (wid & 1) * 64;

    const uint32_t smA_u = s2u(smA), smB_u = s2u(smB);
    const uint32_t abase = smA_u + (uint32_t)(wm + (lane & 15)) * (SP * 2) + (lane >> 4) * 16;
    const uint32_t bbase = smB_u + (uint32_t)(wn + (lane & 7) + ((lane >> 4) << 3)) * (SP * 2)
                                 + ((lane >> 3) & 1) * 16;

    float c[2][8][4];
#pragma unroll
    for (int mt = 0; mt < 2; ++mt)
#pragma unroll
        for (int nt = 0; nt < 8; ++nt)
#pragma unroll
            for (int q = 0; q < 4; ++q) c[mt][nt][q] = 0.f;

#pragma unroll
    for (int ks = 0; ks < 9; ++ks) {
        const uint32_t kb = ks * 32;               // k0*2 bytes
        uint32_t a[2][4];
#pragma unroll
        for (int mt = 0; mt < 2; ++mt)
            asm volatile("ldmatrix.sync.aligned.m8n8.x4.shared.b16 {%0,%1,%2,%3}, [%4];"
                         : "=r"(a[mt][0]), "=r"(a[mt][1]), "=r"(a[mt][2]), "=r"(a[mt][3])
                         : "r"(abase + mt * 16 * (SP * 2) + kb));
#pragma unroll
        for (int ntp = 0; ntp < 4; ++ntp) {
            uint32_t b0, b1, b2, b3;
            asm volatile("ldmatrix.sync.aligned.m8n8.x4.shared.b16 {%0,%1,%2,%3}, [%4];"
                         : "=r"(b0), "=r"(b1), "=r"(b2), "=r"(b3)
                         : "r"(bbase + ntp * 16 * (SP * 2) + kb));
#pragma unroll
            for (int mt = 0; mt < 2; ++mt) {
                asm volatile(
                    "mma.sync.aligned.m16n8k16.row.col.f32.f16.f16.f32 "
                    "{%0,%1,%2,%3}, {%4,%5,%6,%7}, {%8,%9}, {%0,%1,%2,%3};"
                    : "+f"(c[mt][2 * ntp][0]), "+f"(c[mt][2 * ntp][1]),
                      "+f"(c[mt][2 * ntp][2]), "+f"(c[mt][2 * ntp][3])
                    : "r"(a[mt][0]), "r"(a[mt][1]), "r"(a[mt][2]), "r"(a[mt][3]),
                      "r"(b0), "r"(b1));
                asm volatile(
                    "mma.sync.aligned.m16n8k16.row.col.f32.f16.f16.f32 "
                    "{%0,%1,%2,%3}, {%4,%5,%6,%7}, {%8,%9}, {%0,%1,%2,%3};"
                    : "+f"(c[mt][2 * ntp + 1][0]), "+f"(c[mt][2 * ntp + 1][1]),
                      "+f"(c[mt][2 * ntp + 1][2]), "+f"(c[mt][2 * ntp + 1][3])
                    : "r"(a[mt][0]), "r"(a[mt][1]), "r"(a[mt][2]), "r"(a[mt][3]),
                      "r"(b2), "r"(b3));
            }
        }
    }

    // epilogue: relu + store
#pragma unroll
    for (int mt = 0; mt < 2; ++mt) {
        const int row0 = n0 + wm + mt * 16 + (lane >> 2);
#pragma unroll
        for (int nt = 0; nt < 8; ++nt) {
            const int col = wn + nt * 8 + (lane & 3) * 2;
            if (row0 < NN) {
                float2 v;
                v.x = fmaxf(c[mt][nt][0], 0.f);
                v.y = fmaxf(c[mt][nt][1], 0.f);
                *(float2*)(out + (size_t)row0 * HH + col) = v;
            }
            if (row0 + 8 < NN) {
                float2 v;
                v.x = fmaxf(c[mt][nt][2], 0.f);
                v.y = fmaxf(c[mt][nt][3], 0.f);
                *(float2*)(out + (size_t)(row0 + 8) * HH + col) = v;
            }
        }
    }
}

// ------------------------------------------------- launch
extern "C" void kernel_launch(void* const* d_in, const int* in_sizes, int n_in,
                              void* d_out, int out_size) {
    const float* feature = (const float*)d_in[0];
    const float* x       = (const float*)d_in[1];
    const float* label   = (const float*)d_in[2];
    const float* w       = (const float*)d_in[3];
    const float* et      = (const float*)d_in[4];
    const int*   src     = (const int*)  d_in[5];
    const float* W0      = (const float*)d_in[6];
    const float* b0      = (const float*)d_in[7];
    const float* W1      = (const float*)d_in[8];
    const float* b1      = (const float*)d_in[9];
    const float* W2      = (const float*)d_in[10];
    const float* b2      = (const float*)d_in[11];
    const float* Wt3     = (const float*)d_in[12];
    const float* Wt4     = (const float*)d_in[13];
    float* out = (float*)d_out;

    cudaFuncSetAttribute(gemm_kernel, cudaFuncAttributeMaxDynamicSharedMemorySize,
                         GEMM_SMEM);

    pc_kernel<<<NCONV + 142, 256>>>(feature, W0, b0, W1, b1, W2, b2, Wt3, Wt4);
    gather_kernel<<<NN / 8, 256>>>(x, label, w, et, src);      // 3750 blocks
    gemm_kernel<<<NPAD / 128, 256, GEMM_SMEM>>>(out);          // 235 blocks
}

// round 17
// speedup vs baseline: 1.2633x; 1.0078x over previous
#include <cuda_runtime.h>
#include <cuda_fp16.h>
#include <cstdint>

#define NN    30000
#define DD    32
#define HH    128
#define KD    10
#define NPAD  30080          // 235 * 128
#define KPAD  144            // 142 used + 2 zero
#define SP    152            // smem k-pitch in halves (304 B, ldmatrix conflict-free)
#define GEMM_SMEM (2 * 128 * SP * 2)   // 77824 B
#define NF4   (NN * HH / 4)            // 960000 float4 elements
#define NCONV 938                      // convert blocks (4 float4 per thread)

__device__ __half g_feat[NN * HH];          // fp16 feature cache
__device__ __half g_Ah[NPAD * KPAD];        // A fp16 row-major (zero-init)
__device__ __half g_Bth[128 * KPAD];        // B^T fp16 [n][k] (zero-init)

// ------------------------------------------------- convert + prep in one grid
// blocks 0..937: fp32->fp16 feature convert, 4 float4/thread (MLP 4).
// blocks 938..1079: build B^T row r = bid-938 (c-row uses 256-thread split-K).
__global__ void __launch_bounds__(256)
pc_kernel(const float* __restrict__ f,
          const float* __restrict__ W0, const float* __restrict__ b0,
          const float* __restrict__ W1, const float* __restrict__ b1,
          const float* __restrict__ W2, const float* __restrict__ b2,
          const float* __restrict__ Wt3, const float* __restrict__ Wt4) {
    const int bid = blockIdx.x, tid = threadIdx.x;
    if (bid < NCONV) {
        const int base = bid * 1024 + tid;
        float4 v[4];
        int    idx[4];
        bool   ok[4];
#pragma unroll
        for (int u = 0; u < 4; ++u) {
            idx[u] = base + u * 256;
            ok[u]  = idx[u] < NF4;
            v[u]   = ok[u] ? ((const float4*)f)[idx[u]]
                           : make_float4(0.f, 0.f, 0.f, 0.f);
        }
#pragma unroll
        for (int u = 0; u < 4; ++u) {
            if (ok[u]) {
                __half2 h0 = __float22half2_rn(make_float2(v[u].x, v[u].y));
                __half2 h1 = __float22half2_rn(make_float2(v[u].z, v[u].w));
                uint2 o;
                o.x = *(unsigned*)&h0;
                o.y = *(unsigned*)&h1;
                ((uint2*)g_feat)[idx[u]] = o;
            }
        }
        return;
    }
    const int r = bid - NCONV;          // 0..141
    if (r == 140) {                     // c = relu(Wt4) @ Wt3, split-K over 2 halves
        __shared__ float part[256];
        const int j = tid & 127, half = tid >> 7;
        float acc = 0.f;
#pragma unroll 8
        for (int h = half * 64; h < half * 64 + 64; ++h) {
            float t = Wt4[h];
            t = t > 0.f ? t : 0.f;
            acc += t * Wt3[h * HH + j];
        }
        part[tid] = acc;
        __syncthreads();
        if (tid < 128)
            g_Bth[j * KPAD + 140] = __float2half(part[tid] + part[tid + 128]);
        return;
    }
    if (tid >= 128) return;
    const int j = tid;
    float v;
    if (r < 128)        v = W2[r * HH + j];
    else if (r < 130)   v = W0[(r - 128) * HH + j];
    else if (r < 140)   v = W1[(r - 130) * HH + j];
    else                v = b0[j] + b1[j] + b2[j];   // r == 141: bias row
    g_Bth[j * KPAD + r] = __float2half(v);
}

// ------------------------------------------------- gather: 1 warp / node
__global__ void __launch_bounds__(256, 3)
gather_kernel(const float* __restrict__ x,  const float* __restrict__ label,
              const float* __restrict__ w,  const float* __restrict__ et,
              const int*   __restrict__ src) {
    __shared__ float2 meta[8][DD];
    const int wp = threadIdx.x >> 5, lane = threadIdx.x & 31;
    const int n  = blockIdx.x * 8 + wp;            // 3750 * 8 == 30000

    const int base = n * DD + lane;
    int   s_l = src[base];
    float e_l = ((const float2*)et)[base].x;
    float S   = w[base] * e_l;
#pragma unroll
    for (int o = 16; o; o >>= 1) S += __shfl_xor_sync(0xffffffffu, S, o);
    meta[wp][lane] = make_float2(e_l, __int_as_float(s_l));
    __syncwarp();

    const uint2* fp = (const uint2*)g_feat;
    float2 a0 = make_float2(0.f, 0.f), a1 = make_float2(0.f, 0.f);
#pragma unroll
    for (int d = 0; d < DD; ++d) {
        float2 me = meta[wp][d];
        int   s = __float_as_int(me.y);
        float e = me.x;
        uint2 q = __ldg(fp + s * (HH / 4) + lane);
        float2 f0 = __half22float2(*(__half2*)&q.x);
        float2 f1 = __half22float2(*(__half2*)&q.y);
        a0.x += f0.x * e; a0.y += f0.y * e;
        a1.x += f1.x * e; a1.y += f1.y * e;
    }

    __half* Ar = g_Ah + (size_t)n * KPAD;
    {
        __half2 h0 = __float22half2_rn(a0);
        __half2 h1 = __float22half2_rn(a1);
        uint2 o; o.x = *(unsigned*)&h0; o.y = *(unsigned*)&h1;
        *(uint2*)(Ar + lane * 4) = o;              // k = 4*lane .. 4*lane+3
    }
    float ev;
    if (lane < 2)        ev = x[n * 2 + lane];
    else if (lane < 12)  ev = label[n * KD + lane - 2];
    else if (lane == 12) ev = S;
    else                 ev = 1.0f;
    if (lane < 14)
        Ar[128 + lane] = __float2half(ev);         // k = 128..141
}

// ------------------------------------------------- HMMA GEMM: 128x128 tile / CTA
__device__ __forceinline__ uint32_t s2u(const void* p) {
    uint32_t a;
    asm("{ .reg .u64 t; cvta.to.shared.u64 t, %1; cvt.u32.u64 %0, t; }" : "=r"(a) : "l"(p));
    return a;
}

__global__ void __launch_bounds__(256, 2)
gemm_kernel(float* __restrict__ out) {
    extern __shared__ __half sm[];
    __half* smA = sm;                 // [128 m][SP]
    __half* smB = sm + 128 * SP;      // [128 n][SP]

    const int tid  = threadIdx.x;
    const int wid  = tid >> 5, lane = tid & 31;
    const int n0   = blockIdx.x * 128;

    // stage A tile + B tile via cp.async: 2304 float4 each (9 per thread)
    {
        const float4* sAg = (const float4*)(g_Ah + (size_t)n0 * KPAD);
        const float4* sBg = (const float4*)g_Bth;
#pragma unroll
        for (int t = 0; t < 9; ++t) {
            int i = t * 256 + tid;
            int row = i / 18, q = i % 18;          // 18 float4 per 144-half row
            asm volatile("cp.async.cg.shared.global [%0], [%1], 16;"
                         :: "r"(s2u(smA + row * SP + q * 8)), "l"(sAg + i));
            asm volatile("cp.async.cg.shared.global [%0], [%1], 16;"
                         :: "r"(s2u(smB + row * SP + q * 8)), "l"(sBg + i));
        }
        asm volatile("cp.async.commit_group;" ::: "memory");
        asm volatile("cp.async.wait_group 0;" ::: "memory");
    }
    __syncthreads();

    // warp grid: 4 (m) x 2 (n); warp tile 32m x 64n
    const int wm = (wid >> 1) * 32;
    const int wn = (wid & 1) * 64;

    const uint32_t smA_u = s2u(smA), smB_u = s2u(smB);
    const uint32_t abase = smA_u + (uint32_t)(wm + (lane & 15)) * (SP * 2) + (lane >> 4) * 16;
    const uint32_t bbase = smB_u + (uint32_t)(wn + (lane & 7) + ((lane >> 4) << 3)) * (SP * 2)
                                 + ((lane >> 3) & 1) * 16;

    float c[2][8][4];
#pragma unroll
    for (int mt = 0; mt < 2; ++mt)
#pragma unroll
        for (int nt = 0; nt < 8; ++nt)
#pragma unroll
            for (int q = 0; q < 4; ++q) c[mt][nt][q] = 0.f;

#pragma unroll
    for (int ks = 0; ks < 9; ++ks) {
        const uint32_t kb = ks * 32;               // k0*2 bytes
        uint32_t a[2][4];
#pragma unroll
        for (int mt = 0; mt < 2; ++mt)
            asm volatile("ldmatrix.sync.aligned.m8n8.x4.shared.b16 {%0,%1,%2,%3}, [%4];"
                         : "=r"(a[mt][0]), "=r"(a[mt][1]), "=r"(a[mt][2]), "=r"(a[mt][3])
                         : "r"(abase + mt * 16 * (SP * 2) + kb));
#pragma unroll
        for (int ntp = 0; ntp < 4; ++ntp) {
            uint32_t b0, b1, b2, b3;
            asm volatile("ldmatrix.sync.aligned.m8n8.x4.shared.b16 {%0,%1,%2,%3}, [%4];"
                         : "=r"(b0), "=r"(b1), "=r"(b2), "=r"(b3)
                         : "r"(bbase + ntp * 16 * (SP * 2) + kb));
#pragma unroll
            for (int mt = 0; mt < 2; ++mt) {
                asm volatile(
                    "mma.sync.aligned.m16n8k16.row.col.f32.f16.f16.f32 "
                    "{%0,%1,%2,%3}, {%4,%5,%6,%7}, {%8,%9}, {%0,%1,%2,%3};"
                    : "+f"(c[mt][2 * ntp][0]), "+f"(c[mt][2 * ntp][1]),
                      "+f"(c[mt][2 * ntp][2]), "+f"(c[mt][2 * ntp][3])
                    : "r"(a[mt][0]), "r"(a[mt][1]), "r"(a[mt][2]), "r"(a[mt][3]),
                      "r"(b0), "r"(b1));
                asm volatile(
                    "mma.sync.aligned.m16n8k16.row.col.f32.f16.f16.f32 "
                    "{%0,%1,%2,%3}, {%4,%5,%6,%7}, {%8,%9}, {%0,%1,%2,%3};"
                    : "+f"(c[mt][2 * ntp + 1][0]), "+f"(c[mt][2 * ntp + 1][1]),
                      "+f"(c[mt][2 * ntp + 1][2]), "+f"(c[mt][2 * ntp + 1][3])
                    : "r"(a[mt][0]), "r"(a[mt][1]), "r"(a[mt][2]), "r"(a[mt][3]),
                      "r"(b2), "r"(b3));
            }
        }
    }

    // epilogue: relu + store
#pragma unroll
    for (int mt = 0; mt < 2; ++mt) {
        const int row0 = n0 + wm + mt * 16 + (lane >> 2);
#pragma unroll
        for (int nt = 0; nt < 8; ++nt) {
            const int col = wn + nt * 8 + (lane & 3) * 2;
            if (row0 < NN) {
                float2 v;
                v.x = fmaxf(c[mt][nt][0], 0.f);
                v.y = fmaxf(c[mt][nt][1], 0.f);
                *(float2*)(out + (size_t)row0 * HH + col) = v;
            }
            if (row0 + 8 < NN) {
                float2 v;
                v.x = fmaxf(c[mt][nt][2], 0.f);
                v.y = fmaxf(c[mt][nt][3], 0.f);
                *(float2*)(out + (size_t)(row0 + 8) * HH + col) = v;
            }
        }
    }
}

// ------------------------------------------------- launch
extern "C" void kernel_launch(void* const* d_in, const int* in_sizes, int n_in,
                              void* d_out, int out_size) {
    const float* feature = (const float*)d_in[0];
    const float* x       = (const float*)d_in[1];
    const float* label   = (const float*)d_in[2];
    const float* w       = (const float*)d_in[3];
    const float* et      = (const float*)d_in[4];
    const int*   src     = (const int*)  d_in[5];
    const float* W0      = (const float*)d_in[6];
    const float* b0      = (const float*)d_in[7];
    const float* W1      = (const float*)d_in[8];
    const float* b1      = (const float*)d_in[9];
    const float* W2      = (const float*)d_in[10];
    const float* b2      = (const float*)d_in[11];
    const float* Wt3     = (const float*)d_in[12];
    const float* Wt4     = (const float*)d_in[13];
    float* out = (float*)d_out;

    cudaFuncSetAttribute(gemm_kernel, cudaFuncAttributeMaxDynamicSharedMemorySize,
                         GEMM_SMEM);

    pc_kernel<<<NCONV + 142, 256>>>(feature, W0, b0, W1, b1, W2, b2, Wt3, Wt4);
    gather_kernel<<<NN / 8, 256>>>(x, label, w, et, src);      // 3750 blocks
    gemm_kernel<<<NPAD / 128, 256, GEMM_SMEM>>>(out);          // 235 blocks
}